// round 1
// baseline (speedup 1.0000x reference)
#include <cuda_runtime.h>

// LIF neuron with cache term:
//   mem   = mem/TAU + (1 + ALPHA*cache) * x_t
//   spike = (mem - V_TH > 0)
//   mem   = (1-spike)*mem          (hard reset, V_RESET = 0)
//   cache = BETA*cache + (1-spike)
//
// X: [B=32, T=64, N=32768] f32, out spikes same shape.
// Lanes (b, n) independent; recurrence sequential in T only.
// All arithmetic in explicit round-to-nearest intrinsics (no FMA
// contraction) to bit-match the XLA CPU reference — the threshold
// cascades rounding flips down the whole T trajectory otherwise.

constexpr int B = 32;
constexpr int T = 64;
constexpr int N = 32768;
constexpr int N4 = N / 4;           // 8192 float4 per (b, t) row

__device__ __forceinline__ float lif_step(float x, float& mem, float& cache) {
    float d = __fdiv_rn(mem, 5.0f);                         // mem / TAU
    float g = __fadd_rn(1.0f, __fmul_rn(0.1f, cache));      // 1 + ALPHA*cache
    mem = __fadd_rn(d, __fmul_rn(g, x));
    bool fired = (mem > 0.5f);                              // mem - V_TH > 0
    float spike = fired ? 1.0f : 0.0f;
    mem = fired ? 0.0f : mem;                               // hard reset to 0
    cache = __fadd_rn(__fmul_rn(0.5f, cache), 1.0f - spike); // BETA*cache + (1-spike)
    return spike;
}

__global__ __launch_bounds__(256) void lif_kernel(
    const float4* __restrict__ X, float4* __restrict__ out)
{
    int lane = blockIdx.x * blockDim.x + threadIdx.x;   // [0, B*N4)
    int b = lane >> 13;                                  // lane / N4
    int c = lane & (N4 - 1);                             // lane % N4
    int base = b * (T * N4) + c;                         // max 16,777,215 < 2^31

    float4 mem   = make_float4(0.f, 0.f, 0.f, 0.f);
    float4 cache = make_float4(0.f, 0.f, 0.f, 0.f);

#pragma unroll 4
    for (int t = 0; t < T; ++t) {
        int idx = base + t * N4;
        float4 x = X[idx];
        float4 s;
        s.x = lif_step(x.x, mem.x, cache.x);
        s.y = lif_step(x.y, mem.y, cache.y);
        s.z = lif_step(x.z, mem.z, cache.z);
        s.w = lif_step(x.w, mem.w, cache.w);
        out[idx] = s;
    }
}

extern "C" void kernel_launch(void* const* d_in, const int* in_sizes, int n_in,
                              void* d_out, int out_size) {
    const float4* X = (const float4*)d_in[0];
    float4* out = (float4*)d_out;
    int lanes = B * N4;                 // 262,144
    lif_kernel<<<lanes / 256, 256>>>(X, out);
}

// round 2
// speedup vs baseline: 1.8277x; 1.8277x over previous
#include <cuda_runtime.h>

// LIF neuron with cache term:
//   mem   = mem/TAU + (1 + ALPHA*cache) * x_t
//   spike = (mem - V_TH > 0)
//   mem   = (1-spike)*mem          (hard reset, V_RESET = 0)
//   cache = BETA*cache + (1-spike)
//
// X: [B=32, T=64, N=32768] f32, out spikes same shape.
//
// Division by TAU=5 is done with a 3-op FMA sequence that is provably
// bit-identical to correctly-rounded division for every float input
// (residual-corrected Markstein step; for d=5 the true quotient is
// >= 1/10 ulp away from any rounding midpoint while the sequence's
// error is ~2^-25 ulp, so the final single rounding is exact).
// All other arithmetic uses explicit __f*_rn intrinsics to forbid FMA
// contraction, bit-matching the XLA reference — threshold flips would
// otherwise cascade down the T trajectory.

constexpr int B = 32;
constexpr int T = 64;
constexpr int N = 32768;
constexpr int N4 = N / 4;           // 8192 float4 per (b, t) row

__device__ __forceinline__ float div5_exact(float x) {
    const float y = 0.2f;                       // RN(1/5)
    float q = __fmul_rn(x, y);                  // ~1 ulp approx
    float r = __fmaf_rn(q, -5.0f, x);           // exact residual
    return __fmaf_rn(r, y, q);                  // == __fdiv_rn(x, 5.0f)
}

__device__ __forceinline__ float lif_step(float x, float& mem, float& cache) {
    float d = div5_exact(mem);                              // mem / TAU
    float g = __fadd_rn(1.0f, __fmul_rn(0.1f, cache));      // 1 + ALPHA*cache
    mem = __fadd_rn(d, __fmul_rn(g, x));
    bool fired = (mem > 0.5f);                              // mem - V_TH > 0
    float spike = fired ? 1.0f : 0.0f;
    mem = fired ? 0.0f : mem;                               // hard reset to 0
    // cache = 0.5*cache + (1 - spike); 1-spike is exact on {0,1}
    cache = __fadd_rn(__fmul_rn(0.5f, cache), fired ? 0.0f : 1.0f);
    return spike;
}

__global__ __launch_bounds__(256) void lif_kernel(
    const float4* __restrict__ X, float4* __restrict__ out)
{
    int lane = blockIdx.x * blockDim.x + threadIdx.x;   // [0, B*N4)
    int b = lane >> 13;                                  // lane / N4
    int c = lane & (N4 - 1);                             // lane % N4
    int base = b * (T * N4) + c;

    float4 mem   = make_float4(0.f, 0.f, 0.f, 0.f);
    float4 cache = make_float4(0.f, 0.f, 0.f, 0.f);

#pragma unroll 4
    for (int t = 0; t < T; ++t) {
        int idx = base + t * N4;
        float4 x = X[idx];
        float4 s;
        s.x = lif_step(x.x, mem.x, cache.x);
        s.y = lif_step(x.y, mem.y, cache.y);
        s.z = lif_step(x.z, mem.z, cache.z);
        s.w = lif_step(x.w, mem.w, cache.w);
        out[idx] = s;
    }
}

extern "C" void kernel_launch(void* const* d_in, const int* in_sizes, int n_in,
                              void* d_out, int out_size) {
    const float4* X = (const float4*)d_in[0];
    float4* out = (float4*)d_out;
    int lanes = B * N4;                 // 262,144
    lif_kernel<<<lanes / 256, 256>>>(X, out);
}

// round 3
// speedup vs baseline: 1.8683x; 1.0222x over previous
#include <cuda_runtime.h>

// LIF neuron with cache term (see earlier rounds for derivation):
//   mem   = mem/TAU + (1 + ALPHA*cache) * x_t
//   spike = (mem - V_TH > 0)
//   mem   = (1-spike)*mem          (hard reset, V_RESET = 0)
//   cache = BETA*cache + (1-spike)
//
// X: [B=32, T=64, N=32768] f32, out spikes same shape. Pure streaming:
// zero reuse, so both streams use streaming cache hints (__ldcs/__stcs)
// and a prefetch-by-1 pipeline to keep one load always in flight per
// thread behind the ~13-instruction step body.
//
// Division by TAU=5 via residual-corrected FMA triple — provably
// bit-identical to __fdiv_rn(x,5) for all floats (true quotient is
// >= 1/10 ulp from any rounding midpoint; sequence error ~2^-25 ulp).
// All other ops use explicit __f*_rn to forbid FMA contraction and
// bit-match the XLA reference (threshold flips would cascade over T).

constexpr int B = 32;
constexpr int T = 64;
constexpr int N = 32768;
constexpr int N4 = N / 4;           // 8192 float4 per (b, t) row

__device__ __forceinline__ float div5_exact(float x) {
    const float y = 0.2f;                       // RN(1/5)
    float q = __fmul_rn(x, y);
    float r = __fmaf_rn(q, -5.0f, x);           // exact residual
    return __fmaf_rn(r, y, q);                  // == __fdiv_rn(x, 5.0f)
}

__device__ __forceinline__ float lif_step(float x, float& mem, float& cache) {
    float d = div5_exact(mem);                              // mem / TAU
    float g = __fadd_rn(1.0f, __fmul_rn(0.1f, cache));      // 1 + ALPHA*cache
    mem = __fadd_rn(d, __fmul_rn(g, x));
    bool fired = (mem > 0.5f);                              // mem - V_TH > 0
    float spike = fired ? 1.0f : 0.0f;
    mem = fired ? 0.0f : mem;                               // hard reset to 0
    cache = __fadd_rn(__fmul_rn(0.5f, cache), fired ? 0.0f : 1.0f);
    return spike;
}

__global__ __launch_bounds__(256) void lif_kernel(
    const float4* __restrict__ X, float4* __restrict__ out)
{
    int lane = blockIdx.x * blockDim.x + threadIdx.x;   // [0, B*N4)
    int b = lane >> 13;                                  // lane / N4
    int c = lane & (N4 - 1);                             // lane % N4
    int base = b * (T * N4) + c;

    float4 mem   = make_float4(0.f, 0.f, 0.f, 0.f);
    float4 cache = make_float4(0.f, 0.f, 0.f, 0.f);

    // Prefetch pipeline: x holds the data for step t; the load for
    // step t+1 is issued before the step-t compute body.
    float4 x = __ldcs(&X[base]);

#pragma unroll 8
    for (int t = 0; t < T; ++t) {
        int tn = min(t + 1, T - 1);               // branchless clamp
        float4 xn = __ldcs(&X[base + tn * N4]);   // in flight during compute

        float4 s;
        s.x = lif_step(x.x, mem.x, cache.x);
        s.y = lif_step(x.y, mem.y, cache.y);
        s.z = lif_step(x.z, mem.z, cache.z);
        s.w = lif_step(x.w, mem.w, cache.w);

        __stcs(&out[base + t * N4], s);
        x = xn;
    }
}

extern "C" void kernel_launch(void* const* d_in, const int* in_sizes, int n_in,
                              void* d_out, int out_size) {
    const float4* X = (const float4*)d_in[0];
    float4* out = (float4*)d_out;
    int lanes = B * N4;                 // 262,144
    lif_kernel<<<lanes / 256, 256>>>(X, out);
}